// round 15
// baseline (speedup 1.0000x reference)
#include <cuda_runtime.h>
#include <cuda_bf16.h>
#include <cuda_fp16.h>
#include <math.h>
#include <stdint.h>

// ---------------- problem constants ----------------
#define SQ      1024
#define DMODEL  2048
#define NH      16
#define NKV     8
#define HD      128
#define FFD     8192
#define NL      4
#define HISTLEN 1024
#define TTOT    2048
#define VOC     32000
#define KVDT    (NKV*HD*TTOT)

// ---------------- fp32 scratch ----------------
__device__ float g_h[SQ*DMODEL];
__device__ float g_q[SQ*NH*HD];
__device__ float g_kt[SQ*NKV*HD];
__device__ float g_vt[SQ*NKV*HD];
__device__ float g_gate[SQ*FFD];
__device__ float g_up[SQ*FFD];
__device__ float g_last[DMODEL];
__device__ float g_att[(size_t)NH*SQ*HISTLEN];   // 64MB scores
__device__ int   g_idmode;
__device__ int   g_eqmode;

// ---------------- pre-split fp16 hi/lo buffers (uint = fp16x2 pair along K) ----
__device__ unsigned g_wqh[NL*2048*1024], g_wql[NL*2048*1024];
__device__ unsigned g_wkh[NL*1024*1024], g_wkl[NL*1024*1024];
__device__ unsigned g_wvh[NL*1024*1024], g_wvl[NL*1024*1024];
__device__ unsigned g_woh[NL*2048*1024], g_wol[NL*2048*1024];
__device__ unsigned g_wgh[NL*8192*1024], g_wgl[NL*8192*1024];
__device__ unsigned g_wuh[NL*8192*1024], g_wul[NL*8192*1024];
__device__ unsigned g_wdh[NL*2048*4096], g_wdl[NL*2048*4096];
__device__ unsigned g_kth[NL*NKV*65536], g_ktl[NL*NKV*65536];  // [t][d] per kv
__device__ unsigned g_vth[NL*NKV*65536], g_vtl[NL*NKV*65536];  // [d][t] per kv
__device__ unsigned g_hnh[SQ*1024],  g_hnl[SQ*1024];
__device__ unsigned g_qh[SQ*1024],   g_ql[SQ*1024];
__device__ unsigned g_Ph[(size_t)NH*SQ*512], g_Pl[(size_t)NH*SQ*512];
__device__ unsigned g_ctxh[SQ*1024], g_ctxl[SQ*1024];
__device__ unsigned g_guh[SQ*4096],  g_gul[SQ*4096];

// ---------------- helpers ----------------
__device__ __forceinline__ uint32_t pack_split(float a, float b, uint32_t& lo)
{
    __half ha = __float2half_rn(a), hb = __float2half_rn(b);
    __half la = __float2half_rn(a - __half2float(ha));
    __half lb = __float2half_rn(b - __half2float(hb));
    lo = ((uint32_t)__half_as_ushort(lb) << 16) | __half_as_ushort(la);
    return ((uint32_t)__half_as_ushort(hb) << 16) | __half_as_ushort(ha);
}

__device__ __forceinline__ void cpa16(unsigned* dst, const unsigned* src)
{
    uint32_t d = (uint32_t)__cvta_generic_to_shared(dst);
    asm volatile("cp.async.cg.shared.global [%0], [%1], 16;" :: "r"(d), "l"(src));
}

// ---------------- dtype sniffing ----------------
__global__ void sniff_kernel(const void* ids_raw, const void* eq_raw)
{
    if (threadIdx.x != 0 || blockIdx.x != 0) return;
    const int* ii = (const int*)ids_raw;
    bool i64ok = true;
    for (int i = 0; i < 128; i++) {
        int lo = ii[2*i], hi = ii[2*i + 1];
        if (hi != 0 || lo < 0 || lo >= VOC) { i64ok = false; break; }
    }
    if (i64ok) { g_idmode = 1; }
    else {
        bool i32ok = true;
        for (int i = 0; i < 256; i++) {
            int v = ii[i];
            if (v < 0 || v >= VOC) { i32ok = false; break; }
        }
        if (i32ok) g_idmode = 0;
        else {
            const float* ff = (const float*)ids_raw;
            bool f32ok = true;
            for (int i = 0; i < 256; i++) {
                float v = ff[i];
                if (!(v >= 0.f && v < (float)VOC && v == rintf(v))) { f32ok = false; break; }
            }
            g_idmode = f32ok ? 2 : 0;
        }
    }
    const float* ef = (const float*)eq_raw;
    bool ef32 = true;
    for (int i = 0; i < 256; i++) {
        float v = ef[i];
        if (!(v >= 0.f && v <= 255.f && v == rintf(v))) { ef32 = false; break; }
    }
    if (ef32) { g_eqmode = 1; }
    else {
        const int* ei = (const int*)eq_raw;
        bool ei32 = true;
        for (int i = 0; i < 256; i++) {
            int v = ei[i];
            if (v < 0 || v > 255) { ei32 = false; break; }
        }
        g_eqmode = ei32 ? 2 : 0;
    }
}

// ---------------- embedding ----------------
__global__ void embed_kernel(const void* __restrict__ ids_raw,
                             const void* __restrict__ eq_raw,
                             const float* __restrict__ sc,
                             const float* __restrict__ zp,
                             float* __restrict__ h)
{
    int idx = blockIdx.x * blockDim.x + threadIdx.x;
    if (idx >= SQ*DMODEL) return;
    int s = idx >> 11;
    int c = idx & 2047;
    int idm = g_idmode;
    int id;
    if (idm == 0)      id = ((const int*)ids_raw)[s];
    else if (idm == 1) id = (int)((const long long*)ids_raw)[s];
    else               id = (int)((const float*)ids_raw)[s];
    size_t off = (size_t)id * DMODEL + c;
    int em = g_eqmode;
    float qv;
    if (em == 0)      qv = (float)((const unsigned char*)eq_raw)[off];
    else if (em == 1) qv = ((const float*)eq_raw)[off];
    else              qv = (float)((const int*)eq_raw)[off];
    h[idx] = qv * sc[id] + zp[id];
}

// ---------------- transpose-split: in[z][K][N] fp32 -> oh/ol[z][N][K/2] -----
__global__ void wsplit_kernel(const float* __restrict__ in,
                              unsigned* __restrict__ oh, unsigned* __restrict__ ol,
                              int K, int N, long long inz, long long outz)
{
    in += (long long)blockIdx.z * inz;
    oh += (long long)blockIdx.z * outz;
    ol += (long long)blockIdx.z * outz;
    __shared__ float s[64][33];
    int n0 = blockIdx.x * 32, k0 = blockIdx.y * 64;
    int tid = threadIdx.x;
#pragma unroll
    for (int i = 0; i < 8; i++) {
        int f = tid + i * 256;
        int k = f >> 5, n = f & 31;
        s[k][n] = in[(size_t)(k0 + k) * N + n0 + n];
    }
    __syncthreads();
    int Ku = K >> 1;
#pragma unroll
    for (int i = 0; i < 4; i++) {
        int f = tid + i * 256;
        int n = f >> 5, ku = f & 31;
        uint32_t lo_;
        uint32_t hi_ = pack_split(s[2*ku][n], s[2*ku + 1][n], lo_);
        size_t o = (size_t)(n0 + n) * Ku + (k0 >> 1) + ku;
        oh[o] = hi_; ol[o] = lo_;
    }
}

// ---------------- rmsnorm -> split pairs ----------------
__global__ void rmsnorm_split_kernel(const float* __restrict__ x, const float* __restrict__ w,
                                     unsigned* __restrict__ oh, unsigned* __restrict__ ol, int dim)
{
    int row = blockIdx.x;
    const float* xr = x + (size_t)row * dim;
    float ss = 0.f;
    for (int i = threadIdx.x; i < dim; i += blockDim.x) {
        float v = xr[i]; ss += v * v;
    }
#pragma unroll
    for (int o = 16; o > 0; o >>= 1) ss += __shfl_xor_sync(0xffffffffu, ss, o);
    __shared__ float wsum[8];
    if ((threadIdx.x & 31) == 0) wsum[threadIdx.x >> 5] = ss;
    __syncthreads();
    float tot = 0.f;
    for (int k = 0; k < 8; k++) tot += wsum[k];
    float inv = rsqrtf(tot / (float)dim + 1e-6f);
    int du = dim >> 1;
    for (int i = threadIdx.x; i < du; i += blockDim.x) {
        float a = w[2*i] * xr[2*i] * inv;
        float b = w[2*i + 1] * xr[2*i + 1] * inv;
        uint32_t lo_;
        uint32_t hi_ = pack_split(a, b, lo_);
        oh[(size_t)row * du + i] = hi_;
        ol[(size_t)row * du + i] = lo_;
    }
}

// ---------------- fp32 rmsnorm (final norm only) ----------------
__global__ void rmsnorm_kernel(const float* __restrict__ x, const float* __restrict__ w,
                               float* __restrict__ out, int dim)
{
    int row = blockIdx.x;
    const float* xr = x + (size_t)row * dim;
    float ss = 0.f;
    for (int i = threadIdx.x; i < dim; i += blockDim.x) {
        float v = xr[i]; ss += v * v;
    }
#pragma unroll
    for (int o = 16; o > 0; o >>= 1) ss += __shfl_xor_sync(0xffffffffu, ss, o);
    __shared__ float wsum[8];
    if ((threadIdx.x & 31) == 0) wsum[threadIdx.x >> 5] = ss;
    __syncthreads();
    float tot = 0.f;
    int nw = blockDim.x >> 5;
    for (int k = 0; k < nw; k++) tot += wsum[k];
    float inv = rsqrtf(tot / (float)dim + 1e-6f);
    float* orow = out + (size_t)row * dim;
    for (int i = threadIdx.x; i < dim; i += blockDim.x)
        orow[i] = w[i] * xr[i] * inv;
}

// ---------------- mma macro ----------------
#define MMA_F16(C0,C1,C2,C3, A0,A1,A2,A3, B0,B1) \
    asm volatile("mma.sync.aligned.m16n8k16.row.col.f32.f16.f16.f32 " \
        "{%0,%1,%2,%3}, {%4,%5,%6,%7}, {%8,%9}, {%0,%1,%2,%3};" \
        : "+f"(C0), "+f"(C1), "+f"(C2), "+f"(C3) \
        : "r"(A0), "r"(A1), "r"(A2), "r"(A3), "r"(B0), "r"(B1))

// ---------------- cp.async pipelined pre-split GEMM ----------------
// C (+)= A @ B^T, A: hi/lo [M][Ku], B: [N][Ku] (pair-packed along K).
// BM=128 BN=128, stage = 8 uints (16 k-elems), 2-stage cp.async pipeline.
// Row pitch 12 uints (48B, 16B-aligned; banks 12g+t mod 32 distinct).
// mode 0: store fp32; 1: +=; 2: split-store (ldc in uints).
#define PITCH 12
__global__ void __launch_bounds__(256) gemm_sp(
    const unsigned* __restrict__ Ah, const unsigned* __restrict__ Al,
    const unsigned* __restrict__ Bh, const unsigned* __restrict__ Bl,
    float* __restrict__ C, unsigned* __restrict__ Oh, unsigned* __restrict__ Ol,
    int N, int Ku, int ldau, int ldbu, int ldc,
    long long sazu, long long sbzu, long long sczu, int zdivB, int mode)
{
    Ah += (long long)blockIdx.z * sazu;
    Al += (long long)blockIdx.z * sazu;
    long long bz = (long long)(blockIdx.z >> zdivB) * sbzu;
    Bh += bz; Bl += bz;
    if (mode == 2) { Oh += (long long)blockIdx.z * sczu; Ol += (long long)blockIdx.z * sczu; }
    else           { C  += (long long)blockIdx.z * sczu; }

    __shared__ unsigned Ahs[2][128 * PITCH], Als[2][128 * PITCH];
    __shared__ unsigned Bhs[2][128 * PITCH], Bls[2][128 * PITCH];

    int tid  = threadIdx.x;
    int lane = tid & 31;
    int warp = tid >> 5;
    int wm = warp & 3;
    int wn = warp >> 2;
    int g = lane >> 2;
    int t = lane & 3;
    int m0 = blockIdx.y * 128;
    int n0 = blockIdx.x * 128;

    int prow = tid >> 1;            // 0..127
    int poff = (tid & 1) * 4;       // 0 or 4
    const unsigned* pAh = Ah + (size_t)(m0 + prow) * ldau + poff;
    const unsigned* pAl = Al + (size_t)(m0 + prow) * ldau + poff;
    const unsigned* pBh = Bh + (size_t)(n0 + prow) * ldbu + poff;
    const unsigned* pBl = Bl + (size_t)(n0 + prow) * ldbu + poff;
    int pdst = prow * PITCH + poff;

    float acc[2][8][4];
#pragma unroll
    for (int i = 0; i < 2; i++)
#pragma unroll
        for (int j = 0; j < 8; j++)
#pragma unroll
            for (int k = 0; k < 4; k++) acc[i][j][k] = 0.f;

    int nstages = Ku >> 3;

    // prefetch stage 0
    cpa16(&Ahs[0][pdst], pAh);
    cpa16(&Als[0][pdst], pAl);
    cpa16(&Bhs[0][pdst], pBh);
    cpa16(&Bls[0][pdst], pBl);
    asm volatile("cp.async.commit_group;");

    for (int s = 0; s < nstages; s++) {
        if (s + 1 < nstages) {
            int b = (s + 1) & 1;
            int ko = (s + 1) << 3;
            cpa16(&Ahs[b][pdst], pAh + ko);
            cpa16(&Als[b][pdst], pAl + ko);
            cpa16(&Bhs[b][pdst], pBh + ko);
            cpa16(&Bls[b][pdst], pBl + ko);
            asm volatile("cp.async.commit_group;");
            asm volatile("cp.async.wait_group 1;");
        } else {
            asm volatile("cp.async.wait_group 0;");
        }
        __syncthreads();

        const unsigned* __restrict__ Ab = Ahs[s & 1];
        const unsigned* __restrict__ Alb = Als[s & 1];
        const unsigned* __restrict__ Bb = Bhs[s & 1];
        const unsigned* __restrict__ Blb = Bls[s & 1];

        uint32_t ah[2][4], al[2][4];
#pragma unroll
        for (int mt = 0; mt < 2; mt++) {
            int base = (wm * 32 + mt * 16 + g) * PITCH + t;
            ah[mt][0] = Ab[base];
            ah[mt][1] = Ab[base + 8 * PITCH];
            ah[mt][2] = Ab[base + 4];
            ah[mt][3] = Ab[base + 8 * PITCH + 4];
            al[mt][0] = Alb[base];
            al[mt][1] = Alb[base + 8 * PITCH];
            al[mt][2] = Alb[base + 4];
            al[mt][3] = Alb[base + 8 * PITCH + 4];
        }
#pragma unroll
        for (int nt = 0; nt < 8; nt++) {
            int bbase = (wn * 64 + nt * 8 + g) * PITCH + t;
            uint32_t bh0 = Bb[bbase], bh1 = Bb[bbase + 4];
            uint32_t bl0 = Blb[bbase], bl1 = Blb[bbase + 4];
#pragma unroll
            for (int mt = 0; mt < 2; mt++) {
                float* c4 = acc[mt][nt];
                MMA_F16(c4[0], c4[1], c4[2], c4[3],
                        ah[mt][0], ah[mt][1], ah[mt][2], ah[mt][3], bh0, bh1);
                MMA_F16(c4[0], c4[1], c4[2], c4[3],
                        ah[mt][0], ah[mt][1], ah[mt][2], ah[mt][3], bl0, bl1);
                MMA_F16(c4[0], c4[1], c4[2], c4[3],
                        al[mt][0], al[mt][1], al[mt][2], al[mt][3], bh0, bh1);
            }
        }
        __syncthreads();
    }

#pragma unroll
    for (int mt = 0; mt < 2; mt++) {
        int r0 = m0 + wm * 32 + mt * 16 + g;
#pragma unroll
        for (int nt = 0; nt < 8; nt++) {
            int cb = n0 + wn * 64 + nt * 8 + 2 * t;
            float* c4 = acc[mt][nt];
            if (mode == 2) {
                uint32_t lo_;
                uint32_t hi_ = pack_split(c4[0], c4[1], lo_);
                Oh[(size_t)r0 * ldc + (cb >> 1)] = hi_;
                Ol[(size_t)r0 * ldc + (cb >> 1)] = lo_;
                hi_ = pack_split(c4[2], c4[3], lo_);
                Oh[(size_t)(r0 + 8) * ldc + (cb >> 1)] = hi_;
                Ol[(size_t)(r0 + 8) * ldc + (cb >> 1)] = lo_;
            } else {
                float* p0 = C + (size_t)r0 * ldc + cb;
                float* p1 = C + (size_t)(r0 + 8) * ldc + cb;
                if (mode == 1) {
                    float2 o0 = *(float2*)p0, o1 = *(float2*)p1;
                    o0.x += c4[0]; o0.y += c4[1];
                    o1.x += c4[2]; o1.y += c4[3];
                    *(float2*)p0 = o0; *(float2*)p1 = o1;
                } else {
                    *(float2*)p0 = make_float2(c4[0], c4[1]);
                    *(float2*)p1 = make_float2(c4[2], c4[3]);
                }
            }
        }
    }
}

// ---------------- RoPE + q/k rmsnorm ----------------
__global__ void rope_norm_kernel(const float* __restrict__ q, const float* __restrict__ kt,
                                 const float* __restrict__ qn_w, const float* __restrict__ kn_w,
                                 float* __restrict__ kout,
                                 unsigned* __restrict__ qh, unsigned* __restrict__ ql)
{
    int s = blockIdx.x;
    int head = blockIdx.y;
    int d = threadIdx.x;
    bool isq = (head < NH);
    const float* src = isq ? (q  + (size_t)s * NH * HD + head * HD)
                           : (kt + (size_t)s * NKV * HD + (head - NH) * HD);
    float x  = src[d];
    float xp = src[(d < 64) ? d + 64 : d - 64];
    int i2 = d & 63;
    float invf = (float)exp(-log(10000.0) * ((double)(2 * i2) / 128.0));
    float ang = (float)(HISTLEN + s) * invf;
    float c  = __half2float(__float2half((float)cos((double)ang)));
    float sn = __half2float(__float2half((float)sin((double)ang)));
    float r = (d < 64) ? (x * c - xp * sn) : (x * c + xp * sn);

    float ss = r * r;
#pragma unroll
    for (int o = 16; o > 0; o >>= 1) ss += __shfl_xor_sync(0xffffffffu, ss, o);
    __shared__ float wsum[4];
    __shared__ float so[128];
    if ((d & 31) == 0) wsum[d >> 5] = ss;
    __syncthreads();
    float tot = wsum[0] + wsum[1] + wsum[2] + wsum[3];
    float inv = rsqrtf(tot * (1.0f / 128.0f) + 1e-6f);
    float w = isq ? qn_w[d] : kn_w[d];
    float out = w * r * inv;
    so[d] = out;
    __syncthreads();
    if (isq) {
        if (d < 64) {
            uint32_t lo_;
            uint32_t hi_ = pack_split(so[2*d], so[2*d + 1], lo_);
            size_t o = (size_t)s * 1024 + head * 64 + d;
            qh[o] = hi_; ql[o] = lo_;
        }
    } else {
        int kvh = head - NH;
        kout[(size_t)kvh * HD * TTOT + (size_t)d * TTOT + HISTLEN + s] = out;
    }
}

// ---------------- masked softmax -> split P ----------------
__global__ void att_softmax_kernel(const float* __restrict__ P,
                                   unsigned* __restrict__ Ph, unsigned* __restrict__ Pl)
{
    int s = blockIdx.x;
    int h = blockIdx.y;
    const float* row = P + ((size_t)h * SQ + s) * HISTLEN;
    int n = s + 1;
    int tid = threadIdx.x;
    __shared__ float red[8];

    float mx = -1e30f;
    for (int t = tid; t < n; t += 256) mx = fmaxf(mx, row[t]);
#pragma unroll
    for (int o = 16; o > 0; o >>= 1) mx = fmaxf(mx, __shfl_xor_sync(0xffffffffu, mx, o));
    if ((tid & 31) == 0) red[tid >> 5] = mx;
    __syncthreads();
    mx = fmaxf(fmaxf(fmaxf(red[0], red[1]), fmaxf(red[2], red[3])),
               fmaxf(fmaxf(red[4], red[5]), fmaxf(red[6], red[7])));

    float sum = 0.f;
    for (int t = tid; t < n; t += 256) sum += __expf(row[t] - mx);
#pragma unroll
    for (int o = 16; o > 0; o >>= 1) sum += __shfl_xor_sync(0xffffffffu, sum, o);
    __syncthreads();
    if ((tid & 31) == 0) red[tid >> 5] = sum;
    __syncthreads();
    sum = red[0] + red[1] + red[2] + red[3] + red[4] + red[5] + red[6] + red[7];
    float inv = 1.f / sum;

    unsigned* oh = Ph + ((size_t)h * SQ + s) * 512;
    unsigned* ol = Pl + ((size_t)h * SQ + s) * 512;
    for (int t2 = tid; t2 < 512; t2 += 256) {
        float p0 = (2*t2     < n) ? __expf(row[2*t2]     - mx) * inv : 0.f;
        float p1 = (2*t2 + 1 < n) ? __expf(row[2*t2 + 1] - mx) * inv : 0.f;
        uint32_t lo_;
        uint32_t hi_ = pack_split(p0, p1, lo_);
        oh[t2] = hi_; ol[t2] = lo_;
    }
}

// ---------------- cache assembly ----------------
__global__ void copy_khist_kernel(const float* __restrict__ src, float* __restrict__ dst)
{
    int idx = blockIdx.x * blockDim.x + threadIdx.x;
    if (idx >= NKV * HD * HISTLEN) return;
    int t = idx & (HISTLEN - 1);
    int row = idx >> 10;
    dst[(size_t)row * TTOT + t] = src[idx];
}

__global__ void copy_vhist_kernel(const float* __restrict__ src, float* __restrict__ dst)
{
    int idx = blockIdx.x * blockDim.x + threadIdx.x;
    if (idx >= NKV * HISTLEN * HD) return;
    int within = idx & (HISTLEN * HD - 1);
    int kv = idx >> 17;
    dst[(size_t)kv * TTOT * HD + within] = src[idx];
}

__global__ void vscatter_kernel(const float* __restrict__ vt, float* __restrict__ dst)
{
    int idx = blockIdx.x * blockDim.x + threadIdx.x;
    if (idx >= SQ * NKV * HD) return;
    int d = idx & 127;
    int kv = (idx >> 7) & 7;
    int s = idx >> 10;
    dst[(size_t)kv * TTOT * HD + (size_t)(HISTLEN + s) * HD + d] = vt[idx];
}

// ---------------- silu(gate)*up -> split pairs ----------------
__global__ void silu_mul_split_kernel(const float* __restrict__ g, const float* __restrict__ u,
                                      unsigned* __restrict__ oh, unsigned* __restrict__ ol, int n2)
{
    int i = blockIdx.x * blockDim.x + threadIdx.x;
    if (i < n2) {
        float x0 = g[2*i],     x1 = g[2*i + 1];
        float a = (x0 / (1.f + expf(-x0))) * u[2*i];
        float b = (x1 / (1.f + expf(-x1))) * u[2*i + 1];
        uint32_t lo_;
        uint32_t hi_ = pack_split(a, b, lo_);
        oh[i] = hi_; ol[i] = lo_;
    }
}

// ---------------- lm head GEMV ----------------
__global__ void lmhead_kernel(const float* __restrict__ x, const float* __restrict__ W,
                              float* __restrict__ out)
{
    __shared__ float xs[256];
    int v = blockIdx.x * 256 + threadIdx.x;
    float acc = 0.f;
    for (int k0 = 0; k0 < DMODEL; k0 += 256) {
        xs[threadIdx.x] = x[k0 + threadIdx.x];
        __syncthreads();
#pragma unroll 16
        for (int k = 0; k < 256; k++)
            acc += xs[k] * W[(size_t)(k0 + k) * VOC + v];
        __syncthreads();
    }
    if (v < VOC) out[v] = acc;
}

// ---------------- host launcher ----------------
extern "C" void kernel_launch(void* const* d_in, const int* in_sizes, int n_in,
                              void* d_out, int out_size)
{
    int IX[19];
    for (int i = 0; i < 19; i++) IX[i] = i;
    if (n_in >= 19 && in_sizes[0] != 1024) {
        const int amap[19] = {5, 6, 17, 1, 2, 3, 9, 14, 7, 18, 15, 8, 13, 10, 4, 16, 0, 12, 11};
        for (int i = 0; i < 19; i++) IX[i] = amap[i];
    }

    const void*  input_ids   = d_in[IX[0]];
    const float* k_cache     = (const float*)d_in[IX[1]];
    const float* v_cache     = (const float*)d_in[IX[2]];
    const void*  embed_q     = d_in[IX[3]];
    const float* embed_scale = (const float*)d_in[IX[4]];
    const float* embed_zp    = (const float*)d_in[IX[5]];
    const float* ln1_w       = (const float*)d_in[IX[6]];
    const float* q_w         = (const float*)d_in[IX[7]];
    const float* k_w         = (const float*)d_in[IX[8]];
    const float* v_w         = (const float*)d_in[IX[9]];
    const float* qn_w        = (const float*)d_in[IX[10]];
    const float* kn_w        = (const float*)d_in[IX[11]];
    const float* o_w         = (const float*)d_in[IX[12]];
    const float* ln2_w       = (const float*)d_in[IX[13]];
    const float* gate_w      = (const float*)d_in[IX[14]];
    const float* up_w        = (const float*)d_in[IX[15]];
    const float* down_w      = (const float*)d_in[IX[16]];
    const float* norm_w      = (const float*)d_in[IX[17]];
    const float* lm_head_w   = (const float*)d_in[IX[18]];
    float* out = (float*)d_out;

    bool write_caches = (out_size >= (int)(VOC + 8u * KVDT));

    float *h_, *q_, *kt_, *vt_, *gate_, *up_, *last_, *att_;
    cudaGetSymbolAddress((void**)&h_,    g_h);
    cudaGetSymbolAddress((void**)&q_,    g_q);
    cudaGetSymbolAddress((void**)&kt_,   g_kt);
    cudaGetSymbolAddress((void**)&vt_,   g_vt);
    cudaGetSymbolAddress((void**)&gate_, g_gate);
    cudaGetSymbolAddress((void**)&up_,   g_up);
    cudaGetSymbolAddress((void**)&last_, g_last);
    cudaGetSymbolAddress((void**)&att_,  g_att);

    unsigned *wqh,*wql,*wkh,*wkl,*wvh,*wvl,*woh,*wol,*wgh,*wgl,*wuh,*wul,*wdh,*wdl;
    unsigned *kth,*ktl,*vth,*vtl,*hnh,*hnl,*qh,*ql,*Ph,*Pl,*ctxh,*ctxl,*guh,*gul;
    cudaGetSymbolAddress((void**)&wqh, g_wqh); cudaGetSymbolAddress((void**)&wql, g_wql);
    cudaGetSymbolAddress((void**)&wkh, g_wkh); cudaGetSymbolAddress((void**)&wkl, g_wkl);
    cudaGetSymbolAddress((void**)&wvh, g_wvh); cudaGetSymbolAddress((void**)&wvl, g_wvl);
    cudaGetSymbolAddress((void**)&woh, g_woh); cudaGetSymbolAddress((void**)&wol, g_wol);
    cudaGetSymbolAddress((void**)&wgh, g_wgh); cudaGetSymbolAddress((void**)&wgl, g_wgl);
    cudaGetSymbolAddress((void**)&wuh, g_wuh); cudaGetSymbolAddress((void**)&wul, g_wul);
    cudaGetSymbolAddress((void**)&wdh, g_wdh); cudaGetSymbolAddress((void**)&wdl, g_wdl);
    cudaGetSymbolAddress((void**)&kth, g_kth); cudaGetSymbolAddress((void**)&ktl, g_ktl);
    cudaGetSymbolAddress((void**)&vth, g_vth); cudaGetSymbolAddress((void**)&vtl, g_vtl);
    cudaGetSymbolAddress((void**)&hnh, g_hnh); cudaGetSymbolAddress((void**)&hnl, g_hnl);
    cudaGetSymbolAddress((void**)&qh,  g_qh);  cudaGetSymbolAddress((void**)&ql,  g_ql);
    cudaGetSymbolAddress((void**)&Ph,  g_Ph);  cudaGetSymbolAddress((void**)&Pl,  g_Pl);
    cudaGetSymbolAddress((void**)&ctxh,g_ctxh);cudaGetSymbolAddress((void**)&ctxl,g_ctxl);
    cudaGetSymbolAddress((void**)&guh, g_guh); cudaGetSymbolAddress((void**)&gul, g_gul);

    sniff_kernel<<<1, 1>>>(input_ids, embed_q);
    embed_kernel<<<(SQ*DMODEL + 255) / 256, 256>>>(input_ids, embed_q, embed_scale, embed_zp, h_);

    // ---- pre-split all weights ([K][N] -> [N][K/2] hi/lo) ----
    wsplit_kernel<<<dim3((NH*HD)/32,  DMODEL/64, NL), 256>>>(q_w,  wqh, wql, DMODEL, NH*HD,
        (long long)DMODEL*NH*HD,  (long long)(NH*HD)*(DMODEL/2));
    wsplit_kernel<<<dim3((NKV*HD)/32, DMODEL/64, NL), 256>>>(k_w,  wkh, wkl, DMODEL, NKV*HD,
        (long long)DMODEL*NKV*HD, (long long)(NKV*HD)*(DMODEL/2));
    wsplit_kernel<<<dim3((NKV*HD)/32, DMODEL/64, NL), 256>>>(v_w,  wvh, wvl, DMODEL, NKV*HD,
        (long long)DMODEL*NKV*HD, (long long)(NKV*HD)*(DMODEL/2));
    wsplit_kernel<<<dim3(DMODEL/32, (NH*HD)/64, NL), 256>>>(o_w,  woh, wol, NH*HD, DMODEL,
        (long long)(NH*HD)*DMODEL, (long long)DMODEL*(NH*HD/2));
    wsplit_kernel<<<dim3(FFD/32, DMODEL/64, NL), 256>>>(gate_w, wgh, wgl, DMODEL, FFD,
        (long long)DMODEL*FFD, (long long)FFD*(DMODEL/2));
    wsplit_kernel<<<dim3(FFD/32, DMODEL/64, NL), 256>>>(up_w,   wuh, wul, DMODEL, FFD,
        (long long)DMODEL*FFD, (long long)FFD*(DMODEL/2));
    wsplit_kernel<<<dim3(DMODEL/32, FFD/64, NL), 256>>>(down_w, wdh, wdl, FFD, DMODEL,
        (long long)FFD*DMODEL, (long long)DMODEL*(FFD/2));
    wsplit_kernel<<<dim3(HISTLEN/32, HD/64, NL*NKV), 256>>>(k_cache, kth, ktl, HD, HISTLEN,
        (long long)HD*HISTLEN, 65536LL);
    wsplit_kernel<<<dim3(HD/32, HISTLEN/64, NL*NKV), 256>>>(v_cache, vth, vtl, HISTLEN, HD,
        (long long)HISTLEN*HD, 65536LL);

    for (int l = 0; l < NL; l++) {
        float* kout = out + VOC + (size_t)l * KVDT;
        float* vout = out + VOC + (size_t)(NL + l) * KVDT;
        if (!write_caches) { kout = att_; vout = att_ + KVDT; }
        const float* kcl = k_cache + (size_t)l * NKV * HD * HISTLEN;
        const float* vcl = v_cache + (size_t)l * NKV * HISTLEN * HD;

        if (write_caches) {
            copy_khist_kernel<<<(NKV*HD*HISTLEN + 255) / 256, 256>>>(kcl, kout);
            copy_vhist_kernel<<<(NKV*HISTLEN*HD + 255) / 256, 256>>>(vcl, vout);
        }

        rmsnorm_split_kernel<<<SQ, 256>>>(h_, ln1_w + (size_t)l * DMODEL, hnh, hnl, DMODEL);

        gemm_sp<<<dim3((NH*HD)/128, SQ/128, 1), 256>>>(hnh, hnl,
            wqh + (size_t)l*2048*1024, wql + (size_t)l*2048*1024,
            q_, 0, 0, NH*HD, 1024, 1024, 1024, NH*HD, 0, 0, 0, 0, 0);
        gemm_sp<<<dim3((NKV*HD)/128, SQ/128, 1), 256>>>(hnh, hnl,
            wkh + (size_t)l*1024*1024, wkl + (size_t)l*1024*1024,
            kt_, 0, 0, NKV*HD, 1024, 1024, 1024, NKV*HD, 0, 0, 0, 0, 0);
        gemm_sp<<<dim3((NKV*HD)/128, SQ/128, 1), 256>>>(hnh, hnl,
            wvh + (size_t)l*1024*1024, wvl + (size_t)l*1024*1024,
            vt_, 0, 0, NKV*HD, 1024, 1024, 1024, NKV*HD, 0, 0, 0, 0, 0);

        rope_norm_kernel<<<dim3(SQ, NH + NKV), 128>>>(q_, kt_,
            qn_w + (size_t)l * HD, kn_w + (size_t)l * HD, kout, qh, ql);
        if (write_caches)
            vscatter_kernel<<<(SQ*NKV*HD + 255) / 256, 256>>>(vt_, vout);

        gemm_sp<<<dim3(HISTLEN/128, SQ/128, NH), 256>>>(qh, ql,
            kth + (size_t)l*NKV*65536, ktl + (size_t)l*NKV*65536,
            att_, 0, 0, HISTLEN, 64, 1024, 64, HISTLEN,
            64LL, 65536LL, (long long)SQ*HISTLEN, 1, 0);

        att_softmax_kernel<<<dim3(SQ, NH), 256>>>(att_, Ph, Pl);

        gemm_sp<<<dim3(HD/128, SQ/128, NH), 256>>>(Ph, Pl,
            vth + (size_t)l*NKV*65536, vtl + (size_t)l*NKV*65536,
            0, ctxh, ctxl, HD, 512, 512, 512, 1024,
            (long long)SQ*512, 65536LL, 64LL, 1, 2);

        gemm_sp<<<dim3(DMODEL/128, SQ/128, 1), 256>>>(ctxh, ctxl,
            woh + (size_t)l*2048*1024, wol + (size_t)l*2048*1024,
            h_, 0, 0, DMODEL, 1024, 1024, 1024, DMODEL, 0, 0, 0, 0, 1);

        rmsnorm_split_kernel<<<SQ, 256>>>(h_, ln2_w + (size_t)l * DMODEL, hnh, hnl, DMODEL);

        gemm_sp<<<dim3(FFD/128, SQ/128, 1), 256>>>(hnh, hnl,
            wgh + (size_t)l*8192*1024, wgl + (size_t)l*8192*1024,
            gate_, 0, 0, FFD, 1024, 1024, 1024, FFD, 0, 0, 0, 0, 0);
        gemm_sp<<<dim3(FFD/128, SQ/128, 1), 256>>>(hnh, hnl,
            wuh + (size_t)l*8192*1024, wul + (size_t)l*8192*1024,
            up_, 0, 0, FFD, 1024, 1024, 1024, FFD, 0, 0, 0, 0, 0);
        silu_mul_split_kernel<<<(SQ*FFD/2 + 255) / 256, 256>>>(gate_, up_, guh, gul, SQ*FFD/2);
        gemm_sp<<<dim3(DMODEL/128, SQ/128, 1), 256>>>(guh, gul,
            wdh + (size_t)l*2048*4096, wdl + (size_t)l*2048*4096,
            h_, 0, 0, DMODEL, 4096, 4096, 4096, DMODEL, 0, 0, 0, 0, 1);
    }

    rmsnorm_kernel<<<1, 256>>>(h_ + (size_t)(SQ - 1) * DMODEL, norm_w, last_, DMODEL);
    lmhead_kernel<<<VOC / 256, 256>>>(last_, lm_head_w, out);
}

// round 17
// speedup vs baseline: 1.0387x; 1.0387x over previous
#include <cuda_runtime.h>
#include <cuda_bf16.h>
#include <cuda_fp16.h>
#include <math.h>
#include <stdint.h>

// ---------------- problem constants ----------------
#define SQ      1024
#define DMODEL  2048
#define NH      16
#define NKV     8
#define HD      128
#define FFD     8192
#define NL      4
#define HISTLEN 1024
#define TTOT    2048
#define VOC     32000
#define KVDT    (NKV*HD*TTOT)

// ---------------- fp32 scratch ----------------
__device__ float g_h[SQ*DMODEL];
__device__ float g_q[SQ*NH*HD];
__device__ float g_kt[SQ*NKV*HD];
__device__ float g_vt[SQ*NKV*HD];
__device__ float g_gate[SQ*FFD];
__device__ float g_up[SQ*FFD];
__device__ float g_last[DMODEL];
__device__ float g_att[(size_t)NH*SQ*HISTLEN];   // 64MB scores
__device__ int   g_idmode;
__device__ int   g_eqmode;

// ---------------- pre-split fp16 hi/lo buffers (uint = fp16x2 pair along K) ----
__device__ unsigned g_wqh[NL*2048*1024], g_wql[NL*2048*1024];
__device__ unsigned g_wkh[NL*1024*1024], g_wkl[NL*1024*1024];
__device__ unsigned g_wvh[NL*1024*1024], g_wvl[NL*1024*1024];
__device__ unsigned g_woh[NL*2048*1024], g_wol[NL*2048*1024];
__device__ unsigned g_wgh[NL*8192*1024], g_wgl[NL*8192*1024];
__device__ unsigned g_wuh[NL*8192*1024], g_wul[NL*8192*1024];
__device__ unsigned g_wdh[NL*2048*4096], g_wdl[NL*2048*4096];
__device__ unsigned g_kth[NL*NKV*65536], g_ktl[NL*NKV*65536];  // [t][d] per kv
__device__ unsigned g_vth[NL*NKV*65536], g_vtl[NL*NKV*65536];  // [d][t] per kv
__device__ unsigned g_hnh[SQ*1024],  g_hnl[SQ*1024];
__device__ unsigned g_qh[SQ*1024],   g_ql[SQ*1024];
__device__ unsigned g_Ph[(size_t)NH*SQ*512], g_Pl[(size_t)NH*SQ*512];
__device__ unsigned g_ctxh[SQ*1024], g_ctxl[SQ*1024];
__device__ unsigned g_guh[SQ*4096],  g_gul[SQ*4096];

// ---------------- helpers ----------------
__device__ __forceinline__ uint32_t pack_split(float a, float b, uint32_t& lo)
{
    __half ha = __float2half_rn(a), hb = __float2half_rn(b);
    __half la = __float2half_rn(a - __half2float(ha));
    __half lb = __float2half_rn(b - __half2float(hb));
    lo = ((uint32_t)__half_as_ushort(lb) << 16) | __half_as_ushort(la);
    return ((uint32_t)__half_as_ushort(hb) << 16) | __half_as_ushort(ha);
}

// ---------------- dtype sniffing ----------------
__global__ void sniff_kernel(const void* ids_raw, const void* eq_raw)
{
    if (threadIdx.x != 0 || blockIdx.x != 0) return;
    const int* ii = (const int*)ids_raw;
    bool i64ok = true;
    for (int i = 0; i < 128; i++) {
        int lo = ii[2*i], hi = ii[2*i + 1];
        if (hi != 0 || lo < 0 || lo >= VOC) { i64ok = false; break; }
    }
    if (i64ok) { g_idmode = 1; }
    else {
        bool i32ok = true;
        for (int i = 0; i < 256; i++) {
            int v = ii[i];
            if (v < 0 || v >= VOC) { i32ok = false; break; }
        }
        if (i32ok) g_idmode = 0;
        else {
            const float* ff = (const float*)ids_raw;
            bool f32ok = true;
            for (int i = 0; i < 256; i++) {
                float v = ff[i];
                if (!(v >= 0.f && v < (float)VOC && v == rintf(v))) { f32ok = false; break; }
            }
            g_idmode = f32ok ? 2 : 0;
        }
    }
    const float* ef = (const float*)eq_raw;
    bool ef32 = true;
    for (int i = 0; i < 256; i++) {
        float v = ef[i];
        if (!(v >= 0.f && v <= 255.f && v == rintf(v))) { ef32 = false; break; }
    }
    if (ef32) { g_eqmode = 1; }
    else {
        const int* ei = (const int*)eq_raw;
        bool ei32 = true;
        for (int i = 0; i < 256; i++) {
            int v = ei[i];
            if (v < 0 || v > 255) { ei32 = false; break; }
        }
        g_eqmode = ei32 ? 2 : 0;
    }
}

// ---------------- embedding ----------------
__global__ void embed_kernel(const void* __restrict__ ids_raw,
                             const void* __restrict__ eq_raw,
                             const float* __restrict__ sc,
                             const float* __restrict__ zp,
                             float* __restrict__ h)
{
    int idx = blockIdx.x * blockDim.x + threadIdx.x;
    if (idx >= SQ*DMODEL) return;
    int s = idx >> 11;
    int c = idx & 2047;
    int idm = g_idmode;
    int id;
    if (idm == 0)      id = ((const int*)ids_raw)[s];
    else if (idm == 1) id = (int)((const long long*)ids_raw)[s];
    else               id = (int)((const float*)ids_raw)[s];
    size_t off = (size_t)id * DMODEL + c;
    int em = g_eqmode;
    float qv;
    if (em == 0)      qv = (float)((const unsigned char*)eq_raw)[off];
    else if (em == 1) qv = ((const float*)eq_raw)[off];
    else              qv = (float)((const int*)eq_raw)[off];
    h[idx] = qv * sc[id] + zp[id];
}

// ---------------- transpose-split: in[z][K][N] fp32 -> oh/ol[z][N][K/2] -----
__global__ void wsplit_kernel(const float* __restrict__ in,
                              unsigned* __restrict__ oh, unsigned* __restrict__ ol,
                              int K, int N, long long inz, long long outz)
{
    in += (long long)blockIdx.z * inz;
    oh += (long long)blockIdx.z * outz;
    ol += (long long)blockIdx.z * outz;
    __shared__ float s[64][33];
    int n0 = blockIdx.x * 32, k0 = blockIdx.y * 64;
    int tid = threadIdx.x;
#pragma unroll
    for (int i = 0; i < 8; i++) {
        int f = tid + i * 256;
        int k = f >> 5, n = f & 31;
        s[k][n] = in[(size_t)(k0 + k) * N + n0 + n];
    }
    __syncthreads();
    int Ku = K >> 1;
#pragma unroll
    for (int i = 0; i < 4; i++) {
        int f = tid + i * 256;
        int n = f >> 5, ku = f & 31;
        uint32_t lo_;
        uint32_t hi_ = pack_split(s[2*ku][n], s[2*ku + 1][n], lo_);
        size_t o = (size_t)(n0 + n) * Ku + (k0 >> 1) + ku;
        oh[o] = hi_; ol[o] = lo_;
    }
}

// ---------------- rmsnorm -> split pairs ----------------
__global__ void rmsnorm_split_kernel(const float* __restrict__ x, const float* __restrict__ w,
                                     unsigned* __restrict__ oh, unsigned* __restrict__ ol, int dim)
{
    int row = blockIdx.x;
    const float* xr = x + (size_t)row * dim;
    float ss = 0.f;
    for (int i = threadIdx.x; i < dim; i += blockDim.x) {
        float v = xr[i]; ss += v * v;
    }
#pragma unroll
    for (int o = 16; o > 0; o >>= 1) ss += __shfl_xor_sync(0xffffffffu, ss, o);
    __shared__ float wsum[8];
    if ((threadIdx.x & 31) == 0) wsum[threadIdx.x >> 5] = ss;
    __syncthreads();
    float tot = 0.f;
    for (int k = 0; k < 8; k++) tot += wsum[k];
    float inv = rsqrtf(tot / (float)dim + 1e-6f);
    int du = dim >> 1;
    for (int i = threadIdx.x; i < du; i += blockDim.x) {
        float a = w[2*i] * xr[2*i] * inv;
        float b = w[2*i + 1] * xr[2*i + 1] * inv;
        uint32_t lo_;
        uint32_t hi_ = pack_split(a, b, lo_);
        oh[(size_t)row * du + i] = hi_;
        ol[(size_t)row * du + i] = lo_;
    }
}

// ---------------- fp32 rmsnorm (final norm only) ----------------
__global__ void rmsnorm_kernel(const float* __restrict__ x, const float* __restrict__ w,
                               float* __restrict__ out, int dim)
{
    int row = blockIdx.x;
    const float* xr = x + (size_t)row * dim;
    float ss = 0.f;
    for (int i = threadIdx.x; i < dim; i += blockDim.x) {
        float v = xr[i]; ss += v * v;
    }
#pragma unroll
    for (int o = 16; o > 0; o >>= 1) ss += __shfl_xor_sync(0xffffffffu, ss, o);
    __shared__ float wsum[8];
    if ((threadIdx.x & 31) == 0) wsum[threadIdx.x >> 5] = ss;
    __syncthreads();
    float tot = 0.f;
    int nw = blockDim.x >> 5;
    for (int k = 0; k < nw; k++) tot += wsum[k];
    float inv = rsqrtf(tot / (float)dim + 1e-6f);
    float* orow = out + (size_t)row * dim;
    for (int i = threadIdx.x; i < dim; i += blockDim.x)
        orow[i] = w[i] * xr[i] * inv;
}

// ---------------- mma / ldmatrix macros ----------------
#define MMA_F16(C0,C1,C2,C3, A0,A1,A2,A3, B0,B1) \
    asm volatile("mma.sync.aligned.m16n8k16.row.col.f32.f16.f16.f32 " \
        "{%0,%1,%2,%3}, {%4,%5,%6,%7}, {%8,%9}, {%0,%1,%2,%3};" \
        : "+f"(C0), "+f"(C1), "+f"(C2), "+f"(C3) \
        : "r"(A0), "r"(A1), "r"(A2), "r"(A3), "r"(B0), "r"(B1))

#define LDSM4(R0,R1,R2,R3,ADDR) \
    asm volatile("ldmatrix.sync.aligned.m8n8.x4.shared.b16 {%0,%1,%2,%3}, [%4];" \
        : "=r"(R0), "=r"(R1), "=r"(R2), "=r"(R3) : "r"(ADDR))

// ---------------- pre-split GEMM (ldmatrix + triangular skip) ----------------
// C (+)= A @ B^T, A: hi/lo uint arrays [M][Ku], B: [N][Ku] (pair-packed K).
// BM=128 BN=128 BK=32(halves), 256 threads (8 warps 4x2), warp tile 32x64.
// mode 0: store fp32; 1: +=; 2: split-store (ldc in uints).
// tri=1: skip blocks with n0 >= m0+128 (fully masked attention scores).
// kcap=1: cap k-loop at (m0+128)/2 uints (P rows zero beyond t<=s).
#define ROWW 20
__global__ void __launch_bounds__(256) gemm_sp(
    const unsigned* __restrict__ Ah, const unsigned* __restrict__ Al,
    const unsigned* __restrict__ Bh, const unsigned* __restrict__ Bl,
    float* __restrict__ C, unsigned* __restrict__ Oh, unsigned* __restrict__ Ol,
    int N, int Ku, int ldau, int ldbu, int ldc,
    long long sazu, long long sbzu, long long sczu, int zdivB, int mode,
    int tri, int kcap)
{
    int m0 = blockIdx.y * 128;
    int n0 = blockIdx.x * 128;
    if (tri && n0 >= m0 + 128) return;
    int KuEff = kcap ? ((m0 + 128) >> 1) : Ku;

    Ah += (long long)blockIdx.z * sazu;
    Al += (long long)blockIdx.z * sazu;
    long long bz = (long long)(blockIdx.z >> zdivB) * sbzu;
    Bh += bz; Bl += bz;
    if (mode == 2) { Oh += (long long)blockIdx.z * sczu; Ol += (long long)blockIdx.z * sczu; }
    else           { C  += (long long)blockIdx.z * sczu; }

    __shared__ unsigned Ahs[128 * ROWW], Als[128 * ROWW];
    __shared__ unsigned Bhs[128 * ROWW], Bls[128 * ROWW];

    int tid  = threadIdx.x;
    int lane = tid & 31;
    int warp = tid >> 5;
    int wm = warp & 3;
    int wn = warp >> 2;

    uint32_t aBaseH = (uint32_t)__cvta_generic_to_shared(Ahs);
    uint32_t aBaseL = (uint32_t)__cvta_generic_to_shared(Als);
    uint32_t bBaseH = (uint32_t)__cvta_generic_to_shared(Bhs);
    uint32_t bBaseL = (uint32_t)__cvta_generic_to_shared(Bls);

    // ldmatrix lane address components
    int arow = lane & 15;
    int aword = (lane >> 4) << 2;
    int brow = (lane & 7) + ((lane >> 4) << 3);
    int bword = ((lane >> 3) & 1) << 2;

    float acc[2][8][4];
#pragma unroll
    for (int i = 0; i < 2; i++)
#pragma unroll
        for (int j = 0; j < 8; j++)
#pragma unroll
            for (int k = 0; k < 4; k++) acc[i][j][k] = 0.f;

    for (int ku0 = 0; ku0 < KuEff; ku0 += 16) {
#pragma unroll
        for (int i = 0; i < 2; i++) {
            int f = tid + i * 256;
            int r = f >> 2;
            int q4 = (f & 3) << 2;
            *(uint4*)&Ahs[r * ROWW + q4] = *(const uint4*)(Ah + (size_t)(m0 + r) * ldau + ku0 + q4);
            *(uint4*)&Als[r * ROWW + q4] = *(const uint4*)(Al + (size_t)(m0 + r) * ldau + ku0 + q4);
            *(uint4*)&Bhs[r * ROWW + q4] = *(const uint4*)(Bh + (size_t)(n0 + r) * ldbu + ku0 + q4);
            *(uint4*)&Bls[r * ROWW + q4] = *(const uint4*)(Bl + (size_t)(n0 + r) * ldbu + ku0 + q4);
        }
        __syncthreads();

#pragma unroll
        for (int ks = 0; ks < 2; ks++) {
            int kw = ks * 8;
            uint32_t ah[2][4], al[2][4];
#pragma unroll
            for (int mt = 0; mt < 2; mt++) {
                uint32_t ao = (uint32_t)(((wm * 32 + mt * 16 + arow) * ROWW + kw + aword) * 4);
                LDSM4(ah[mt][0], ah[mt][1], ah[mt][2], ah[mt][3], aBaseH + ao);
                LDSM4(al[mt][0], al[mt][1], al[mt][2], al[mt][3], aBaseL + ao);
            }
#pragma unroll
            for (int pr = 0; pr < 4; pr++) {
                uint32_t bo = (uint32_t)(((wn * 64 + pr * 16 + brow) * ROWW + kw + bword) * 4);
                uint32_t bh0a, bh1a, bh0b, bh1b, bl0a, bl1a, bl0b, bl1b;
                LDSM4(bh0a, bh1a, bh0b, bh1b, bBaseH + bo);
                LDSM4(bl0a, bl1a, bl0b, bl1b, bBaseL + bo);
#pragma unroll
                for (int mt = 0; mt < 2; mt++) {
                    float* cA = acc[mt][2 * pr];
                    MMA_F16(cA[0], cA[1], cA[2], cA[3],
                            ah[mt][0], ah[mt][1], ah[mt][2], ah[mt][3], bh0a, bh1a);
                    MMA_F16(cA[0], cA[1], cA[2], cA[3],
                            ah[mt][0], ah[mt][1], ah[mt][2], ah[mt][3], bl0a, bl1a);
                    MMA_F16(cA[0], cA[1], cA[2], cA[3],
                            al[mt][0], al[mt][1], al[mt][2], al[mt][3], bh0a, bh1a);
                    float* cB = acc[mt][2 * pr + 1];
                    MMA_F16(cB[0], cB[1], cB[2], cB[3],
                            ah[mt][0], ah[mt][1], ah[mt][2], ah[mt][3], bh0b, bh1b);
                    MMA_F16(cB[0], cB[1], cB[2], cB[3],
                            ah[mt][0], ah[mt][1], ah[mt][2], ah[mt][3], bl0b, bl1b);
                    MMA_F16(cB[0], cB[1], cB[2], cB[3],
                            al[mt][0], al[mt][1], al[mt][2], al[mt][3], bh0b, bh1b);
                }
            }
        }
        __syncthreads();
    }

    int g = lane >> 2;
    int t = lane & 3;
#pragma unroll
    for (int mt = 0; mt < 2; mt++) {
        int r0 = m0 + wm * 32 + mt * 16 + g;
#pragma unroll
        for (int nt = 0; nt < 8; nt++) {
            int cb = n0 + wn * 64 + nt * 8 + 2 * t;
            float* c4 = acc[mt][nt];
            if (mode == 2) {
                uint32_t lo_;
                uint32_t hi_ = pack_split(c4[0], c4[1], lo_);
                Oh[(size_t)r0 * ldc + (cb >> 1)] = hi_;
                Ol[(size_t)r0 * ldc + (cb >> 1)] = lo_;
                hi_ = pack_split(c4[2], c4[3], lo_);
                Oh[(size_t)(r0 + 8) * ldc + (cb >> 1)] = hi_;
                Ol[(size_t)(r0 + 8) * ldc + (cb >> 1)] = lo_;
            } else {
                float* p0 = C + (size_t)r0 * ldc + cb;
                float* p1 = C + (size_t)(r0 + 8) * ldc + cb;
                if (mode == 1) {
                    float2 o0 = *(float2*)p0, o1 = *(float2*)p1;
                    o0.x += c4[0]; o0.y += c4[1];
                    o1.x += c4[2]; o1.y += c4[3];
                    *(float2*)p0 = o0; *(float2*)p1 = o1;
                } else {
                    *(float2*)p0 = make_float2(c4[0], c4[1]);
                    *(float2*)p1 = make_float2(c4[2], c4[3]);
                }
            }
        }
    }
}

// ---------------- RoPE + q/k rmsnorm ----------------
__global__ void rope_norm_kernel(const float* __restrict__ q, const float* __restrict__ kt,
                                 const float* __restrict__ qn_w, const float* __restrict__ kn_w,
                                 float* __restrict__ kout,
                                 unsigned* __restrict__ qh, unsigned* __restrict__ ql)
{
    int s = blockIdx.x;
    int head = blockIdx.y;
    int d = threadIdx.x;
    bool isq = (head < NH);
    const float* src = isq ? (q  + (size_t)s * NH * HD + head * HD)
                           : (kt + (size_t)s * NKV * HD + (head - NH) * HD);
    float x  = src[d];
    float xp = src[(d < 64) ? d + 64 : d - 64];
    int i2 = d & 63;
    float invf = (float)exp(-log(10000.0) * ((double)(2 * i2) / 128.0));
    float ang = (float)(HISTLEN + s) * invf;
    float c  = __half2float(__float2half((float)cos((double)ang)));
    float sn = __half2float(__float2half((float)sin((double)ang)));
    float r = (d < 64) ? (x * c - xp * sn) : (x * c + xp * sn);

    float ss = r * r;
#pragma unroll
    for (int o = 16; o > 0; o >>= 1) ss += __shfl_xor_sync(0xffffffffu, ss, o);
    __shared__ float wsum[4];
    __shared__ float so[128];
    if ((d & 31) == 0) wsum[d >> 5] = ss;
    __syncthreads();
    float tot = wsum[0] + wsum[1] + wsum[2] + wsum[3];
    float inv = rsqrtf(tot * (1.0f / 128.0f) + 1e-6f);
    float w = isq ? qn_w[d] : kn_w[d];
    float out = w * r * inv;
    so[d] = out;
    __syncthreads();
    if (isq) {
        if (d < 64) {
            uint32_t lo_;
            uint32_t hi_ = pack_split(so[2*d], so[2*d + 1], lo_);
            size_t o = (size_t)s * 1024 + head * 64 + d;
            qh[o] = hi_; ql[o] = lo_;
        }
    } else {
        int kvh = head - NH;
        kout[(size_t)kvh * HD * TTOT + (size_t)d * TTOT + HISTLEN + s] = out;
    }
}

// ---------------- masked softmax -> split P ----------------
__global__ void att_softmax_kernel(const float* __restrict__ P,
                                   unsigned* __restrict__ Ph, unsigned* __restrict__ Pl)
{
    int s = blockIdx.x;
    int h = blockIdx.y;
    const float* row = P + ((size_t)h * SQ + s) * HISTLEN;
    int n = s + 1;
    int tid = threadIdx.x;
    __shared__ float red[8];

    float mx = -1e30f;
    for (int t = tid; t < n; t += 256) mx = fmaxf(mx, row[t]);
#pragma unroll
    for (int o = 16; o > 0; o >>= 1) mx = fmaxf(mx, __shfl_xor_sync(0xffffffffu, mx, o));
    if ((tid & 31) == 0) red[tid >> 5] = mx;
    __syncthreads();
    mx = fmaxf(fmaxf(fmaxf(red[0], red[1]), fmaxf(red[2], red[3])),
               fmaxf(fmaxf(red[4], red[5]), fmaxf(red[6], red[7])));

    float sum = 0.f;
    for (int t = tid; t < n; t += 256) sum += __expf(row[t] - mx);
#pragma unroll
    for (int o = 16; o > 0; o >>= 1) sum += __shfl_xor_sync(0xffffffffu, sum, o);
    __syncthreads();
    if ((tid & 31) == 0) red[tid >> 5] = sum;
    __syncthreads();
    sum = red[0] + red[1] + red[2] + red[3] + red[4] + red[5] + red[6] + red[7];
    float inv = 1.f / sum;

    unsigned* oh = Ph + ((size_t)h * SQ + s) * 512;
    unsigned* ol = Pl + ((size_t)h * SQ + s) * 512;
    for (int t2 = tid; t2 < 512; t2 += 256) {
        float p0 = (2*t2     < n) ? __expf(row[2*t2]     - mx) * inv : 0.f;
        float p1 = (2*t2 + 1 < n) ? __expf(row[2*t2 + 1] - mx) * inv : 0.f;
        uint32_t lo_;
        uint32_t hi_ = pack_split(p0, p1, lo_);
        oh[t2] = hi_; ol[t2] = lo_;
    }
}

// ---------------- cache assembly ----------------
__global__ void copy_khist_kernel(const float* __restrict__ src, float* __restrict__ dst)
{
    int idx = blockIdx.x * blockDim.x + threadIdx.x;
    if (idx >= NKV * HD * HISTLEN) return;
    int t = idx & (HISTLEN - 1);
    int row = idx >> 10;
    dst[(size_t)row * TTOT + t] = src[idx];
}

__global__ void copy_vhist_kernel(const float* __restrict__ src, float* __restrict__ dst)
{
    int idx = blockIdx.x * blockDim.x + threadIdx.x;
    if (idx >= NKV * HISTLEN * HD) return;
    int within = idx & (HISTLEN * HD - 1);
    int kv = idx >> 17;
    dst[(size_t)kv * TTOT * HD + within] = src[idx];
}

__global__ void vscatter_kernel(const float* __restrict__ vt, float* __restrict__ dst)
{
    int idx = blockIdx.x * blockDim.x + threadIdx.x;
    if (idx >= SQ * NKV * HD) return;
    int d = idx & 127;
    int kv = (idx >> 7) & 7;
    int s = idx >> 10;
    dst[(size_t)kv * TTOT * HD + (size_t)(HISTLEN + s) * HD + d] = vt[idx];
}

// ---------------- silu(gate)*up -> split pairs ----------------
__global__ void silu_mul_split_kernel(const float* __restrict__ g, const float* __restrict__ u,
                                      unsigned* __restrict__ oh, unsigned* __restrict__ ol, int n2)
{
    int i = blockIdx.x * blockDim.x + threadIdx.x;
    if (i < n2) {
        float x0 = g[2*i],     x1 = g[2*i + 1];
        float a = (x0 / (1.f + expf(-x0))) * u[2*i];
        float b = (x1 / (1.f + expf(-x1))) * u[2*i + 1];
        uint32_t lo_;
        uint32_t hi_ = pack_split(a, b, lo_);
        oh[i] = hi_; ol[i] = lo_;
    }
}

// ---------------- lm head GEMV ----------------
__global__ void lmhead_kernel(const float* __restrict__ x, const float* __restrict__ W,
                              float* __restrict__ out)
{
    __shared__ float xs[256];
    int v = blockIdx.x * 256 + threadIdx.x;
    float acc = 0.f;
    for (int k0 = 0; k0 < DMODEL; k0 += 256) {
        xs[threadIdx.x] = x[k0 + threadIdx.x];
        __syncthreads();
#pragma unroll 16
        for (int k = 0; k < 256; k++)
            acc += xs[k] * W[(size_t)(k0 + k) * VOC + v];
        __syncthreads();
    }
    if (v < VOC) out[v] = acc;
}

// ---------------- host launcher ----------------
extern "C" void kernel_launch(void* const* d_in, const int* in_sizes, int n_in,
                              void* d_out, int out_size)
{
    int IX[19];
    for (int i = 0; i < 19; i++) IX[i] = i;
    if (n_in >= 19 && in_sizes[0] != 1024) {
        const int amap[19] = {5, 6, 17, 1, 2, 3, 9, 14, 7, 18, 15, 8, 13, 10, 4, 16, 0, 12, 11};
        for (int i = 0; i < 19; i++) IX[i] = amap[i];
    }

    const void*  input_ids   = d_in[IX[0]];
    const float* k_cache     = (const float*)d_in[IX[1]];
    const float* v_cache     = (const float*)d_in[IX[2]];
    const void*  embed_q     = d_in[IX[3]];
    const float* embed_scale = (const float*)d_in[IX[4]];
    const float* embed_zp    = (const float*)d_in[IX[5]];
    const float* ln1_w       = (const float*)d_in[IX[6]];
    const float* q_w         = (const float*)d_in[IX[7]];
    const float* k_w         = (const float*)d_in[IX[8]];
    const float* v_w         = (const float*)d_in[IX[9]];
    const float* qn_w        = (const float*)d_in[IX[10]];
    const float* kn_w        = (const float*)d_in[IX[11]];
    const float* o_w         = (const float*)d_in[IX[12]];
    const float* ln2_w       = (const float*)d_in[IX[13]];
    const float* gate_w      = (const float*)d_in[IX[14]];
    const float* up_w        = (const float*)d_in[IX[15]];
    const float* down_w      = (const float*)d_in[IX[16]];
    const float* norm_w      = (const float*)d_in[IX[17]];
    const float* lm_head_w   = (const float*)d_in[IX[18]];
    float* out = (float*)d_out;

    bool write_caches = (out_size >= (int)(VOC + 8u * KVDT));

    float *h_, *q_, *kt_, *vt_, *gate_, *up_, *last_, *att_;
    cudaGetSymbolAddress((void**)&h_,    g_h);
    cudaGetSymbolAddress((void**)&q_,    g_q);
    cudaGetSymbolAddress((void**)&kt_,   g_kt);
    cudaGetSymbolAddress((void**)&vt_,   g_vt);
    cudaGetSymbolAddress((void**)&gate_, g_gate);
    cudaGetSymbolAddress((void**)&up_,   g_up);
    cudaGetSymbolAddress((void**)&last_, g_last);
    cudaGetSymbolAddress((void**)&att_,  g_att);

    unsigned *wqh,*wql,*wkh,*wkl,*wvh,*wvl,*woh,*wol,*wgh,*wgl,*wuh,*wul,*wdh,*wdl;
    unsigned *kth,*ktl,*vth,*vtl,*hnh,*hnl,*qh,*ql,*Ph,*Pl,*ctxh,*ctxl,*guh,*gul;
    cudaGetSymbolAddress((void**)&wqh, g_wqh); cudaGetSymbolAddress((void**)&wql, g_wql);
    cudaGetSymbolAddress((void**)&wkh, g_wkh); cudaGetSymbolAddress((void**)&wkl, g_wkl);
    cudaGetSymbolAddress((void**)&wvh, g_wvh); cudaGetSymbolAddress((void**)&wvl, g_wvl);
    cudaGetSymbolAddress((void**)&woh, g_woh); cudaGetSymbolAddress((void**)&wol, g_wol);
    cudaGetSymbolAddress((void**)&wgh, g_wgh); cudaGetSymbolAddress((void**)&wgl, g_wgl);
    cudaGetSymbolAddress((void**)&wuh, g_wuh); cudaGetSymbolAddress((void**)&wul, g_wul);
    cudaGetSymbolAddress((void**)&wdh, g_wdh); cudaGetSymbolAddress((void**)&wdl, g_wdl);
    cudaGetSymbolAddress((void**)&kth, g_kth); cudaGetSymbolAddress((void**)&ktl, g_ktl);
    cudaGetSymbolAddress((void**)&vth, g_vth); cudaGetSymbolAddress((void**)&vtl, g_vtl);
    cudaGetSymbolAddress((void**)&hnh, g_hnh); cudaGetSymbolAddress((void**)&hnl, g_hnl);
    cudaGetSymbolAddress((void**)&qh,  g_qh);  cudaGetSymbolAddress((void**)&ql,  g_ql);
    cudaGetSymbolAddress((void**)&Ph,  g_Ph);  cudaGetSymbolAddress((void**)&Pl,  g_Pl);
    cudaGetSymbolAddress((void**)&ctxh,g_ctxh);cudaGetSymbolAddress((void**)&ctxl,g_ctxl);
    cudaGetSymbolAddress((void**)&guh, g_guh); cudaGetSymbolAddress((void**)&gul, g_gul);

    sniff_kernel<<<1, 1>>>(input_ids, embed_q);
    embed_kernel<<<(SQ*DMODEL + 255) / 256, 256>>>(input_ids, embed_q, embed_scale, embed_zp, h_);

    // ---- pre-split all weights ([K][N] -> [N][K/2] hi/lo) ----
    wsplit_kernel<<<dim3((NH*HD)/32,  DMODEL/64, NL), 256>>>(q_w,  wqh, wql, DMODEL, NH*HD,
        (long long)DMODEL*NH*HD,  (long long)(NH*HD)*(DMODEL/2));
    wsplit_kernel<<<dim3((NKV*HD)/32, DMODEL/64, NL), 256>>>(k_w,  wkh, wkl, DMODEL, NKV*HD,
        (long long)DMODEL*NKV*HD, (long long)(NKV*HD)*(DMODEL/2));
    wsplit_kernel<<<dim3((NKV*HD)/32, DMODEL/64, NL), 256>>>(v_w,  wvh, wvl, DMODEL, NKV*HD,
        (long long)DMODEL*NKV*HD, (long long)(NKV*HD)*(DMODEL/2));
    wsplit_kernel<<<dim3(DMODEL/32, (NH*HD)/64, NL), 256>>>(o_w,  woh, wol, NH*HD, DMODEL,
        (long long)(NH*HD)*DMODEL, (long long)DMODEL*(NH*HD/2));
    wsplit_kernel<<<dim3(FFD/32, DMODEL/64, NL), 256>>>(gate_w, wgh, wgl, DMODEL, FFD,
        (long long)DMODEL*FFD, (long long)FFD*(DMODEL/2));
    wsplit_kernel<<<dim3(FFD/32, DMODEL/64, NL), 256>>>(up_w,   wuh, wul, DMODEL, FFD,
        (long long)DMODEL*FFD, (long long)FFD*(DMODEL/2));
    wsplit_kernel<<<dim3(DMODEL/32, FFD/64, NL), 256>>>(down_w, wdh, wdl, FFD, DMODEL,
        (long long)FFD*DMODEL, (long long)DMODEL*(FFD/2));
    wsplit_kernel<<<dim3(HISTLEN/32, HD/64, NL*NKV), 256>>>(k_cache, kth, ktl, HD, HISTLEN,
        (long long)HD*HISTLEN, 65536LL);
    wsplit_kernel<<<dim3(HD/32, HISTLEN/64, NL*NKV), 256>>>(v_cache, vth, vtl, HISTLEN, HD,
        (long long)HISTLEN*HD, 65536LL);

    for (int l = 0; l < NL; l++) {
        float* kout = out + VOC + (size_t)l * KVDT;
        float* vout = out + VOC + (size_t)(NL + l) * KVDT;
        if (!write_caches) { kout = att_; vout = att_ + KVDT; }
        const float* kcl = k_cache + (size_t)l * NKV * HD * HISTLEN;
        const float* vcl = v_cache + (size_t)l * NKV * HISTLEN * HD;

        if (write_caches) {
            copy_khist_kernel<<<(NKV*HD*HISTLEN + 255) / 256, 256>>>(kcl, kout);
            copy_vhist_kernel<<<(NKV*HISTLEN*HD + 255) / 256, 256>>>(vcl, vout);
        }

        rmsnorm_split_kernel<<<SQ, 256>>>(h_, ln1_w + (size_t)l * DMODEL, hnh, hnl, DMODEL);

        gemm_sp<<<dim3((NH*HD)/128, SQ/128, 1), 256>>>(hnh, hnl,
            wqh + (size_t)l*2048*1024, wql + (size_t)l*2048*1024,
            q_, 0, 0, NH*HD, 1024, 1024, 1024, NH*HD, 0, 0, 0, 0, 0, 0, 0);
        gemm_sp<<<dim3((NKV*HD)/128, SQ/128, 1), 256>>>(hnh, hnl,
            wkh + (size_t)l*1024*1024, wkl + (size_t)l*1024*1024,
            kt_, 0, 0, NKV*HD, 1024, 1024, 1024, NKV*HD, 0, 0, 0, 0, 0, 0, 0);
        gemm_sp<<<dim3((NKV*HD)/128, SQ/128, 1), 256>>>(hnh, hnl,
            wvh + (size_t)l*1024*1024, wvl + (size_t)l*1024*1024,
            vt_, 0, 0, NKV*HD, 1024, 1024, 1024, NKV*HD, 0, 0, 0, 0, 0, 0, 0);

        rope_norm_kernel<<<dim3(SQ, NH + NKV), 128>>>(q_, kt_,
            qn_w + (size_t)l * HD, kn_w + (size_t)l * HD, kout, qh, ql);
        if (write_caches)
            vscatter_kernel<<<(SQ*NKV*HD + 255) / 256, 256>>>(vt_, vout);

        // scores (triangular skip: blocks with n0 >= m0+128 are fully masked)
        gemm_sp<<<dim3(HISTLEN/128, SQ/128, NH), 256>>>(qh, ql,
            kth + (size_t)l*NKV*65536, ktl + (size_t)l*NKV*65536,
            att_, 0, 0, HISTLEN, 64, 1024, 64, HISTLEN,
            64LL, 65536LL, (long long)SQ*HISTLEN, 1, 0, 1, 0);

        att_softmax_kernel<<<dim3(SQ, NH), 256>>>(att_, Ph, Pl);

        // ctx (k-loop capped: P rows zero beyond t <= s)
        gemm_sp<<<dim3(HD/128, SQ/128, NH), 256>>>(Ph, Pl,
            vth + (size_t)l*NKV*65536, vtl + (size_t)l*NKV*65536,
            0, ctxh, ctxl, HD, 512, 512, 512, 1024,
            (long long)SQ*512, 65536LL, 64LL, 1, 2, 0, 1);

        gemm_sp<<<dim3(DMODEL/128, SQ/128, 1), 256>>>(ctxh, ctxl,
            woh + (size_t)l*2048*1024, wol + (size_t)l*2048*1024,
            h_, 0, 0, DMODEL, 1024, 1024, 1024, DMODEL, 0, 0, 0, 0, 1, 0, 0);

        rmsnorm_split_kernel<<<SQ, 256>>>(h_, ln2_w + (size_t)l * DMODEL, hnh, hnl, DMODEL);

        gemm_sp<<<dim3(FFD/128, SQ/128, 1), 256>>>(hnh, hnl,
            wgh + (size_t)l*8192*1024, wgl + (size_t)l*8192*1024,
            gate_, 0, 0, FFD, 1024, 1024, 1024, FFD, 0, 0, 0, 0, 0, 0, 0);
        gemm_sp<<<dim3(FFD/128, SQ/128, 1), 256>>>(hnh, hnl,
            wuh + (size_t)l*8192*1024, wul + (size_t)l*8192*1024,
            up_, 0, 0, FFD, 1024, 1024, 1024, FFD, 0, 0, 0, 0, 0, 0, 0);
        silu_mul_split_kernel<<<(SQ*FFD/2 + 255) / 256, 256>>>(gate_, up_, guh, gul, SQ*FFD/2);
        gemm_sp<<<dim3(DMODEL/128, SQ/128, 1), 256>>>(guh, gul,
            wdh + (size_t)l*2048*4096, wdl + (size_t)l*2048*4096,
            h_, 0, 0, DMODEL, 4096, 4096, 4096, DMODEL, 0, 0, 0, 0, 1, 0, 0);
    }

    rmsnorm_kernel<<<1, 256>>>(h_ + (size_t)(SQ - 1) * DMODEL, norm_w, last_, DMODEL);
    lmhead_kernel<<<VOC / 256, 256>>>(last_, lm_head_w, out);
}